// round 3
// baseline (speedup 1.0000x reference)
#include <cuda_runtime.h>
#include <cstdint>

// Problem constants
#define BB 64
#define HH 128
#define WW 128
#define CC 16
#define UU 256
#define HWN (HH * WW)          // 16384

typedef unsigned long long ull;

// ---------------- scratch (device globals; no allocation allowed) ----------------
__device__ float g_S[HWN * BB];                 // S_t[hw][b], 4 MB
__device__ float g_GX1t[WW * UU];               // [w][u]
__device__ float g_GX2t[WW * UU];
__device__ float g_GY1t[HH * UU];               // [h][u], c1 folded in
__device__ float g_GY2t[HH * UU];               // [h][u], -c2 folded in
__device__ float g_P[HH * BB * UU];             // partials [h][b][u], 8 MB

// ---------------- packed-fp32 helpers (guarded; fallback = scalar fmaf) ----------
__device__ __forceinline__ ull dup2(float s) {
    ull d; unsigned r = __float_as_uint(s);
    asm("mov.b64 %0, {%1, %1};" : "=l"(d) : "r"(r));
    return d;
}
__device__ __forceinline__ float f2lo(ull v) { return __uint_as_float((unsigned)v); }
__device__ __forceinline__ float f2hi(ull v) { return __uint_as_float((unsigned)(v >> 32)); }
__device__ __forceinline__ ull pack2(float lo, float hi) {
    ull d;
    asm("mov.b64 %0, {%1, %2};" : "=l"(d) : "r"(__float_as_uint(lo)), "r"(__float_as_uint(hi)));
    return d;
}
__device__ __forceinline__ void fma2(ull& d, ull a, ull b) {
#if defined(__CUDA_ARCH__) && (__CUDA_ARCH__ >= 1000)
    asm("fma.rn.f32x2 %0, %1, %2, %0;" : "+l"(d) : "l"(a), "l"(b));
#else
    float lo = fmaf(f2lo(a), f2lo(b), f2lo(d));
    float hi = fmaf(f2hi(a), f2hi(b), f2hi(d));
    d = pack2(lo, hi);
#endif
}

// ============================================================================
// K1: channel reduction + transpose.  S_t[(h*W+w)][b] = sum_c x[b][h][w][c]
// grid 256 blocks x 256 thr; block handles 64 consecutive hw for all 64 b.
// Reads fully coalesced (consecutive threads = consecutive float4), quad-shuffle
// reduces the 16 channels (4 float4 held by 4 adjacent lanes).
// ============================================================================
__global__ __launch_bounds__(256) void k1_reduce_c(const float* __restrict__ x) {
    const int hw0 = blockIdx.x * 64;
    __shared__ float s_s[64][65];
    const float4* x4 = reinterpret_cast<const float4*>(x);
    const int tid = threadIdx.x;

    #pragma unroll 4
    for (int b = 0; b < 64; b++) {
        // per b: 64 hw * 4 float4 = 256 float4, one per thread
        float4 v = x4[(size_t)b * (HWN * 4) + hw0 * 4 + tid];
        float s = v.x + v.y + v.z + v.w;
        s += __shfl_xor_sync(0xffffffffu, s, 1);
        s += __shfl_xor_sync(0xffffffffu, s, 2);
        if ((tid & 3) == 0) s_s[tid >> 2][b] = s;
    }
    __syncthreads();
    #pragma unroll
    for (int j = 0; j < 4; j++) {
        int idx = tid + (j << 8);          // 0..1023
        int l = idx >> 4;                  // local hw
        int b4 = (idx & 15) << 2;          // b quad
        float4 o = make_float4(s_s[l][b4], s_s[l][b4 + 1], s_s[l][b4 + 2], s_s[l][b4 + 3]);
        *reinterpret_cast<float4*>(&g_S[(size_t)(hw0 + l) * 64 + b4]) = o;
    }
}

// ============================================================================
// K2: separable Gaussian tables.  grid 128 (coord t) x 256 (u).
//   GX1[w][u] = exp(-(w-ux)^2/2/s1)          GX2: sigma = s1+s2
//   GY1[h][u] =  a1/(2*pi*s1)      * exp(-(h-uy)^2/2/s1)
//   GY2[h][u] = -a2/(2*pi*(s1+s2)) * exp(-(h-uy)^2/2/(s1+s2))
// ============================================================================
__global__ __launch_bounds__(256) void k2_tables(
    const float* __restrict__ a1, const float* __restrict__ a2,
    const float* __restrict__ s1, const float* __restrict__ s2,
    const float* __restrict__ ux, const float* __restrict__ uy)
{
    const int t = blockIdx.x;        // coordinate (W == H == 128)
    const int u = threadIdx.x;
    const float TWO_PI = 6.2831853071795864769f;

    float sA = s1[u];
    float sB = sA + s2[u];
    float c1 = a1[u] / (sA * TWO_PI);
    float c2 = a2[u] / (sB * TWO_PI);
    float ft = (float)t;

    float dx = ft - ux[u];
    float dx2 = 0.5f * dx * dx;
    g_GX1t[t * UU + u] = expf(-dx2 / sA);
    g_GX2t[t * UU + u] = expf(-dx2 / sB);

    float dy = ft - uy[u];
    float dy2 = 0.5f * dy * dy;
    g_GY1t[t * UU + u] =  c1 * expf(-dy2 / sA);
    g_GY2t[t * UU + u] = -c2 * expf(-dy2 / sB);
}

// ============================================================================
// K3: fused filter-build + GEMM.  One block per h row (grid 128).
// Block tile: M=64 (all b) x N=256 (all u), K=128 (w) chunked into 4x32.
// Static SMEM (40 KB): F_s[32][256] built on the fly per chunk, S_s[32][64].
// Thread tile 8b x 8u, inner loop in packed fp32 (fma.rn.f32x2).
// Writes partials g_P[h][b][u] (deterministic; reduced by K4).
// ============================================================================
#define KCH 32
__global__ __launch_bounds__(256) void k3_gemm() {
    __shared__ float F_s[KCH * UU];          // 32 KB
    __shared__ float S_s[KCH * BB];          //  8 KB

    const int h = blockIdx.x;
    const int tid = threadIdx.x;
    const int tu = tid & 31;                 // u octet: u = tu*8..tu*8+7
    const int tb = tid >> 5;                 // b octet: b = tb*8..tb*8+7

    // per-thread filter row factors (u = tid)
    const float gy1 = g_GY1t[h * UU + tid];
    const float gy2 = g_GY2t[h * UU + tid];

    ull acc[8][4];
    #pragma unroll
    for (int b = 0; b < 8; b++)
        #pragma unroll
        for (int p = 0; p < 4; p++) acc[b][p] = 0ull;

    const float* Fb = F_s + tu * 8;
    const float* Sb = S_s + tb * 8;
    const float4* Ssrc = reinterpret_cast<const float4*>(g_S + (size_t)h * (WW * BB));
    float4* Sdst = reinterpret_cast<float4*>(S_s);

    for (int kc = 0; kc < 4; kc++) {
        // ---- build F chunk: thread owns column u = tid, rows j=0..31 ----
        #pragma unroll 8
        for (int j = 0; j < KCH; j++) {
            const int w = kc * KCH + j;
            F_s[j * UU + tid] = fmaf(gy2, g_GX2t[w * UU + tid],
                                     gy1 * g_GX1t[w * UU + tid]);
        }
        // ---- load S chunk: 32*64 floats = 512 float4, 2 per thread ----
        Sdst[tid]       = Ssrc[kc * 512 + tid];
        Sdst[tid + 256] = Ssrc[kc * 512 + tid + 256];
        __syncthreads();

        // ---- register-tiled GEMM over this chunk ----
        #pragma unroll 4
        for (int k = 0; k < KCH; k++) {
            const float4 sA  = *reinterpret_cast<const float4*>(Sb + k * BB);
            const float4 sBv = *reinterpret_cast<const float4*>(Sb + k * BB + 4);
            const ulonglong2 fA = *reinterpret_cast<const ulonglong2*>(Fb + k * UU);
            const ulonglong2 fB = *reinterpret_cast<const ulonglong2*>(Fb + k * UU + 4);
            ull f[4] = { fA.x, fA.y, fB.x, fB.y };
            float sv[8] = { sA.x, sA.y, sA.z, sA.w, sBv.x, sBv.y, sBv.z, sBv.w };
            #pragma unroll
            for (int b = 0; b < 8; b++) {
                ull sd = dup2(sv[b]);
                #pragma unroll
                for (int p = 0; p < 4; p++) fma2(acc[b][p], sd, f[p]);
            }
        }
        __syncthreads();
    }

    // ---- write partials ----
    float* Pp = g_P + (size_t)h * (BB * UU) + (tb * 8) * UU + tu * 8;
    #pragma unroll
    for (int b = 0; b < 8; b++) {
        float4 o0 = make_float4(f2lo(acc[b][0]), f2hi(acc[b][0]), f2lo(acc[b][1]), f2hi(acc[b][1]));
        float4 o1 = make_float4(f2lo(acc[b][2]), f2hi(acc[b][2]), f2lo(acc[b][3]), f2hi(acc[b][3]));
        *reinterpret_cast<float4*>(Pp + b * UU)     = o0;
        *reinterpret_cast<float4*>(Pp + b * UU + 4) = o1;
    }
}

// ============================================================================
// K4: reduce 128 h-partials + bias.  grid 128 x 128 (one thread per output).
// ============================================================================
__global__ __launch_bounds__(128) void k4_reduce(const float* __restrict__ bias,
                                                 float* __restrict__ out) {
    const int idx = blockIdx.x * 128 + threadIdx.x;   // 0..16383
    const int u = idx & 255;
    float s = bias[u];
    #pragma unroll 8
    for (int h = 0; h < HH; h++) s += g_P[h * (BB * UU) + idx];
    out[idx] = s;
}

// ============================================================================
extern "C" void kernel_launch(void* const* d_in, const int* in_sizes, int n_in,
                              void* d_out, int out_size) {
    const float* x    = (const float*)d_in[0];
    const float* a1   = (const float*)d_in[1];
    const float* a2   = (const float*)d_in[2];
    const float* s1   = (const float*)d_in[3];
    const float* s2   = (const float*)d_in[4];
    const float* ux   = (const float*)d_in[5];
    const float* uy   = (const float*)d_in[6];
    const float* bias = (const float*)d_in[7];
    float* out = (float*)d_out;

    k1_reduce_c<<<HWN / 64, 256>>>(x);
    k2_tables<<<128, 256>>>(a1, a2, s1, s2, ux, uy);
    k3_gemm<<<HH, 256>>>();
    k4_reduce<<<128, 128>>>(bias, out);
}